// round 11
// baseline (speedup 1.0000x reference)
#include <cuda_runtime.h>
#include <cstdint>

// ---------------------------------------------------------------------------
// Problem constants
// ---------------------------------------------------------------------------
#define T_STEPS 100
#define B_SZ    32
#define NIN     512
#define N_NEU   2048
#define A_AR    2
#define NC      4096                    // A*N output columns, c = a*2048+n
#define KROWS   4608                    // NIN + NC input rows
#define KCHUNK  144                     // 4608 / 32 k-chunks
#define NKC     32                      // number of k-chunks
#define NBY     8                       // k-split groups (4 chunks each)
#define NBG     4                       // batch groups of 8
#define SLAB    32                      // rows per shared staging slab
#define XIS_SZ  (T_STEPS * B_SZ * NIN)  // 1,638,400
#define SS_SZ   (T_STEPS * B_SZ * N_NEU)// 6,553,600 per area
// alpha = float32(exp(-0.1))
#define ALPHA_F 0.9048374180359595731642491f

// ---------------------------------------------------------------------------
// Device-global scratch (static — no allocation anywhere)
// ---------------------------------------------------------------------------
__device__ float    g_W[KROWS * NC];            // fused weights [k][c]
__device__ float    g_V[B_SZ * NC];             // membrane V [b][c]
__device__ float    g_P[NBY * B_SZ * NC];       // partials [by][b][c]
__device__ unsigned g_mff32[T_STEPS * NIN];     // ff spike masks per t: bit b = batch b
__device__ unsigned g_m32[KROWS];               // current-step masks [k]: bit b = batch b

// ---------------------------------------------------------------------------
// Packed f32x2 helpers (sm_103a) — immune to fast-math contraction
// ---------------------------------------------------------------------------
__device__ __forceinline__ unsigned long long pack2(unsigned lo, unsigned hi) {
    unsigned long long d;
    asm("mov.b64 %0, {%1, %2};" : "=l"(d) : "r"(lo), "r"(hi));
    return d;
}
__device__ __forceinline__ unsigned long long ffma2(unsigned long long a,
                                                    unsigned long long b,
                                                    unsigned long long c) {
    unsigned long long d;
    asm("fma.rn.f32x2 %0, %1, %2, %3;" : "=l"(d) : "l"(a), "l"(b), "l"(c));
    return d;
}
__device__ __forceinline__ unsigned long long fadd2(unsigned long long a,
                                                    unsigned long long b) {
    unsigned long long d;
    asm("add.rn.f32x2 %0, %1, %2;" : "=l"(d) : "l"(a), "l"(b));
    return d;
}
__device__ __forceinline__ float lo32(unsigned long long v) {
    return __uint_as_float((unsigned)v);
}
__device__ __forceinline__ float hi32(unsigned long long v) {
    return __uint_as_float((unsigned)(v >> 32));
}
// cp.async helpers
__device__ __forceinline__ void cp16(unsigned dst, const void* src) {
    asm volatile("cp.async.cg.shared.global [%0], [%1], 16;" :: "r"(dst), "l"(src));
}
__device__ __forceinline__ void cp_commit() {
    asm volatile("cp.async.commit_group;");
}
template <int N> __device__ __forceinline__ void cp_wait() {
    asm volatile("cp.async.wait_group %0;" :: "n"(N));
}

// ---------------------------------------------------------------------------
// Kernel 1: Poisson input spikes for all T -> Xis output region [t][b][i].
// ---------------------------------------------------------------------------
__global__ void __launch_bounds__(256) prep_spikes(const float* __restrict__ rates,
                                                   const float* __restrict__ noise,
                                                   float* __restrict__ out) {
    int idx = blockIdx.x * blockDim.x + threadIdx.x;
    if (idx >= XIS_SZ) return;
    float rt = rates[idx];
    float nz = noise[idx];
    out[idx] = (nz < __fmul_rn(rt, 1e-3f)) ? 1.0f : 0.0f;
}

// ---------------------------------------------------------------------------
// Kernel 1b: pack ff spike masks: g_mff32[t*NIN+i] bit b = spike(batch b).
// ---------------------------------------------------------------------------
__global__ void __launch_bounds__(256) prep_masks(const float* __restrict__ out) {
    int idx = blockIdx.x * blockDim.x + threadIdx.x;    // t*NIN
    if (idx >= T_STEPS * NIN) return;
    int t = idx / NIN;
    int i = idx - t * NIN;
    unsigned m = 0;
#pragma unroll
    for (int b = 0; b < B_SZ; b++) {
        float f = out[t * (B_SZ * NIN) + b * NIN + i];
        m |= (f != 0.0f ? 1u : 0u) << b;
    }
    g_mff32[idx] = m;
}

// ---------------------------------------------------------------------------
// Kernel 2: fuse Win [A,NIN,N] and Wrec [S,A,N,N] into g_W[k][c].
// ---------------------------------------------------------------------------
__global__ void pack_w(const float* __restrict__ Win,
                       const float* __restrict__ Wrec) {
    const int total4 = KROWS * NC / 4;
    for (int idx = blockIdx.x * blockDim.x + threadIdx.x; idx < total4;
         idx += gridDim.x * blockDim.x) {
        int e = idx << 2;
        int k = e >> 12;              // / 4096
        int c = e & (NC - 1);
        int a = c >> 11;
        int n = c & (N_NEU - 1);
        float4 v;
        if (k < NIN) {
            v = *(const float4*)&Win[(a * NIN + k) * N_NEU + n];
        } else {
            int kr = k - NIN;
            int s  = kr >> 11;
            int m  = kr & (N_NEU - 1);
            v = *(const float4*)&Wrec[(((s * A_AR + a) * N_NEU) + m) * (size_t)N_NEU + n];
        }
        *(float4*)&g_W[e] = v;
    }
}

// ---------------------------------------------------------------------------
// Kernel 3: init: V = 0; g_m32 = [mff32(t=0) | zero rec masks].
// ---------------------------------------------------------------------------
__global__ void __launch_bounds__(256) init_state() {
    int idx = blockIdx.x * blockDim.x + threadIdx.x;
    if (idx < KROWS) g_m32[idx] = (idx < NIN) ? g_mff32[idx] : 0u;
    if (idx < B_SZ * NC) g_V[idx] = 0.0f;
}

// ---------------------------------------------------------------------------
// Kernel B (per step): shared-slab sparse GEMM, all 32 batches per block.
// Grid: (32 ct of 128 cols, 8 by). Block: 8 warps = (bg 0..3) x (col-half 2).
// Compaction: warps 0..3 compact chunk by*4+w: union active list (m32 != 0,
//   ascending k) + per-bg sublists (union pos | byte<<16, ascending).
// Main: per chunk, union rows streamed through a double-buffered 32-row
//   shared slab (cp.async, coalesced 512B/row, loaded ONCE for all 4 bgs);
//   warp (bg,ch) consumes only rows with its byte != 0, ascending, expanding
//   byte bits to exact {0.0f,1.0f}. Chunk fold via run/cur registers:
//   ((A0+A1)+A2)+A3 — the identical fadd2 sequence of the old ksub fold.
// Epilogue: coalesced STG.64 partials to g_P[by][b][c].
// ---------------------------------------------------------------------------
__global__ void __launch_bounds__(256, 3) step_gemm(int t) {
    __shared__ unsigned short klist[4][KCHUNK];       // union k, ascending
    __shared__ unsigned       sub[4][NBG][KCHUNK];    // pos | byte<<16
    __shared__ int            ucnt[4];
    __shared__ int            bcnt[4][NBG];
    __shared__ float          stage[2][SLAB][128];

    const int tid  = threadIdx.x;
    const int w    = tid >> 5;
    const int lane = tid & 31;
    const int bg   = w & 3;
    const int ch   = w >> 2;
    const int ct   = blockIdx.x;
    const int by   = blockIdx.y;
    const int c0   = ct * 128;
    const int mycol = c0 + ch * 64 + lane * 2;

    // ---- Compaction: warps 0..3, chunk by*4 + w ----
    if (w < 4) {
        const int kc = by * 4 + w;
        const int k0 = kc * KCHUNK;
        int tu = 0;
        int tb0 = 0, tb1 = 0, tb2 = 0, tb3 = 0;
#pragma unroll
        for (int it = 0; it < 5; it++) {
            int r = it * 32 + lane;
            unsigned m = (r < KCHUNK) ? g_m32[k0 + r] : 0u;
            unsigned bal = __ballot_sync(0xFFFFFFFFu, m != 0u);
            int posu = tu + __popc(bal & ((1u << lane) - 1u));
            if (m != 0u) klist[w][posu] = (unsigned short)(k0 + r);
#pragma unroll
            for (int g = 0; g < NBG; g++) {
                unsigned byte = (m >> (g * 8)) & 0xFFu;
                unsigned balb = __ballot_sync(0xFFFFFFFFu, byte != 0u);
                int* tb = (g == 0) ? &tb0 : (g == 1) ? &tb1 : (g == 2) ? &tb2 : &tb3;
                if (byte != 0u) {
                    int pb = *tb + __popc(balb & ((1u << lane) - 1u));
                    sub[w][g][pb] = (unsigned)posu | (byte << 16);
                }
                *tb += __popc(balb);
            }
            tu += __popc(bal);
        }
        if (lane == 0) {
            ucnt[w] = tu;
            bcnt[w][0] = tb0; bcnt[w][1] = tb1; bcnt[w][2] = tb2; bcnt[w][3] = tb3;
        }
    }
    __syncthreads();

    // ---- Main loop: 4 chunks sequential, slab-staged union rows ----
    unsigned long long run[2][4], cur[2][4];
#pragma unroll
    for (int c = 0; c < 2; c++)
#pragma unroll
        for (int j = 0; j < 4; j++) { run[c][j] = 0ull; cur[c][j] = 0ull; }

    const unsigned stage_base = (unsigned)__cvta_generic_to_shared(&stage[0][0][0]);

    for (int ck = 0; ck < 4; ck++) {
        const int cnt = ucnt[ck];
        const int nb  = bcnt[ck][bg];
        const unsigned* __restrict__ sl = sub[ck][bg];
#pragma unroll
        for (int c = 0; c < 2; c++)
#pragma unroll
            for (int j = 0; j < 4; j++) cur[c][j] = 0ull;

        if (cnt > 0) {
            const int nsl = (cnt + SLAB - 1) / SLAB;
            // issue slab 0 into buffer 0
            {
#pragma unroll
                for (int q = 0; q < 4; q++) {
                    int l = tid + q * 256;          // 0..1023
                    int row = l >> 5;               // 0..31
                    int seg = l & 31;               // 16B segment
                    if (row < cnt) {
                        unsigned k = klist[ck][row];
                        const char* src = (const char*)g_W +
                            (size_t)k * (NC * 4) + (unsigned)(c0 * 4 + seg * 16);
                        cp16(stage_base + (unsigned)(row * 512 + seg * 16), src);
                    }
                }
                cp_commit();
            }
            int j = 0;
            for (int s = 0; s < nsl; s++) {
                if (s + 1 < nsl) {
                    const int base = (s + 1) * SLAB;
                    const unsigned dstb = stage_base +
                        (unsigned)(((s + 1) & 1) * SLAB * 512);
#pragma unroll
                    for (int q = 0; q < 4; q++) {
                        int l = tid + q * 256;
                        int row = l >> 5;
                        int seg = l & 31;
                        if (base + row < cnt) {
                            unsigned k = klist[ck][base + row];
                            const char* src = (const char*)g_W +
                                (size_t)k * (NC * 4) + (unsigned)(c0 * 4 + seg * 16);
                            cp16(dstb + (unsigned)(row * 512 + seg * 16), src);
                        }
                    }
                    cp_commit();
                    cp_wait<1>();
                } else {
                    cp_wait<0>();
                }
                __syncthreads();   // slab s fully staged

                const int bound = (s + 1) * SLAB;
                const int sb = (s & 1);
                const int srow0 = s * SLAB;
                while (j < nb) {
                    unsigned e = sl[j];
                    int pos = (int)(e & 0xFFFFu);
                    if (pos >= bound) break;
                    unsigned byte = e >> 16;
                    float2 wv = *(const float2*)&stage[sb][pos - srow0][ch * 64 + lane * 2];
                    unsigned long long w2a = pack2(__float_as_uint(wv.x), __float_as_uint(wv.x));
                    unsigned long long w2b = pack2(__float_as_uint(wv.y), __float_as_uint(wv.y));
#pragma unroll
                    for (int jj = 0; jj < 4; jj++) {
                        unsigned slo = ((byte >> (2 * jj)) & 1u) ? 0x3f800000u : 0u;
                        unsigned shi = ((byte >> (2 * jj + 1)) & 1u) ? 0x3f800000u : 0u;
                        unsigned long long s2 = pack2(slo, shi);
                        cur[0][jj] = ffma2(w2a, s2, cur[0][jj]);
                        cur[1][jj] = ffma2(w2b, s2, cur[1][jj]);
                    }
                    j++;
                }
                __syncthreads();   // all warps done with slab s; buffer reusable
            }
        }

        if (ck == 0) {
#pragma unroll
            for (int c = 0; c < 2; c++)
#pragma unroll
                for (int j = 0; j < 4; j++) run[c][j] = cur[c][j];
        } else {
#pragma unroll
            for (int c = 0; c < 2; c++)
#pragma unroll
                for (int j = 0; j < 4; j++) run[c][j] = fadd2(run[c][j], cur[c][j]);
        }
    }

    // ---- Epilogue: partials to g_P[by][b][c], coalesced STG.64 ----
#pragma unroll
    for (int jj = 0; jj < 4; jj++) {
        int b = bg * 8 + 2 * jj;
        float2 lo2 = make_float2(lo32(run[0][jj]), lo32(run[1][jj]));
        float2 hi2 = make_float2(hi32(run[0][jj]), hi32(run[1][jj]));
        *(float2*)&g_P[(unsigned)((by * B_SZ + b)     * NC) + mycol] = lo2;
        *(float2*)&g_P[(unsigned)((by * B_SZ + b + 1) * NC) + mycol] = hi2;
    }
}

// ---------------------------------------------------------------------------
// Kernel C (per step): thread = (bg, c) owns 8 batches. Ordered by-ascending
// reduce of 8 partials, LIF update, threshold, output spikes, mask byte
// write into g_m32, ff mask byte copy for t+1. All accesses coalesced/cheap.
// ---------------------------------------------------------------------------
__global__ void __launch_bounds__(256) step_update(float* __restrict__ out, int t) {
    int idx = blockIdx.x * blockDim.x + threadIdx.x;   // 0 .. 16383
    if (idx >= NBG * NC) return;
    int bg = idx >> 12;
    int c  = idx & (NC - 1);
    int a  = c >> 11;
    int n  = c & (N_NEU - 1);

    unsigned char* m8 = (unsigned char*)g_m32;
    unsigned oldm = m8[(NIN + c) * 4 + bg];   // previous spikes (8 batches)
    unsigned newm = 0;

#pragma unroll
    for (int b8 = 0; b8 < 8; b8++) {
        int b = bg * 8 + b8;
        float I = g_P[(0 * B_SZ + b) * NC + c];
#pragma unroll
        for (int by = 1; by < NBY; by++)
            I = __fadd_rn(I, g_P[(by * B_SZ + b) * NC + c]);

        float xd   = (oldm >> b8) & 1u ? 1.0f : 0.0f;
        float Vold = g_V[b * NC + c];
        float Vnew = __fadd_rn(__fmul_rn(__fmul_rn(ALPHA_F, Vold),
                                         __fsub_rn(1.0f, xd)), I);
        unsigned s = Vnew >= 1.0f ? 1u : 0u;
        g_V[b * NC + c] = Vnew;
        newm |= s << b8;
        out[XIS_SZ + a * SS_SZ + t * (B_SZ * N_NEU) + b * N_NEU + n] =
            s ? 1.0f : 0.0f;
    }

    m8[(NIN + c) * 4 + bg] = (unsigned char)newm;   // recurrent byte for t+1
    if (c < NIN && t + 1 < T_STEPS)
        m8[c * 4 + bg] =
            ((const unsigned char*)g_mff32)[((t + 1) * NIN + c) * 4 + bg];
}

// ---------------------------------------------------------------------------
// Launch: prep (4 kernels) + 100 x (gemm, update). Graph-capturable.
// ---------------------------------------------------------------------------
extern "C" void kernel_launch(void* const* d_in, const int* in_sizes, int n_in,
                              void* d_out, int out_size) {
    const float* rates = (const float*)d_in[0];
    const float* noise = (const float*)d_in[1];
    const float* Win   = (const float*)d_in[2];
    const float* Wrec  = (const float*)d_in[3];
    float* out = (float*)d_out;

    prep_spikes<<<(XIS_SZ + 255) / 256, 256>>>(rates, noise, out);
    prep_masks<<<(T_STEPS * NIN + 255) / 256, 256>>>(out);
    pack_w<<<1024, 256>>>(Win, Wrec);
    init_state<<<(B_SZ * NC + 255) / 256, 256>>>();

    for (int t = 0; t < T_STEPS; t++) {
        step_gemm<<<dim3(32, NBY), 256>>>(t);
        step_update<<<(NBG * NC + 255) / 256, 256>>>(out, t);
    }
}

// round 12
// speedup vs baseline: 1.9925x; 1.9925x over previous
#include <cuda_runtime.h>
#include <cstdint>

// ---------------------------------------------------------------------------
// Problem constants
// ---------------------------------------------------------------------------
#define T_STEPS 100
#define B_SZ    32
#define NIN     512
#define N_NEU   2048
#define A_AR    2
#define NC      4096                    // A*N output columns, c = a*2048+n
#define KROWS   4608                    // NIN + NC input rows
#define KCHUNK  144                     // 4608 / 32 k-chunks
#define NKC     32                      // number of k-chunks
#define NBY     8                       // k-splits (4 chunks each)
#define NBG     4                       // batch groups of 8
#define XIS_SZ  (T_STEPS * B_SZ * NIN)  // 1,638,400
#define SS_SZ   (T_STEPS * B_SZ * N_NEU)// 6,553,600 per area
// alpha = float32(exp(-0.1))
#define ALPHA_F 0.9048374180359595731642491f

// ---------------------------------------------------------------------------
// Device-global scratch (static — no allocation anywhere)
// ---------------------------------------------------------------------------
__device__ float         g_W[KROWS * NC];              // fused weights [k][c]
__device__ float         g_V[B_SZ * NC];               // membrane V [b][c]
__device__ float         g_P[NBY * B_SZ * NC];         // partials [by][b][c]
__device__ unsigned char g_mff[T_STEPS * NBG * NIN];   // ff spike masks per t
__device__ unsigned char g_m8[NBG * KROWS];            // current-step masks [bg][k]

// ---------------------------------------------------------------------------
// Packed f32x2 helpers (sm_103a) — immune to fast-math contraction
// ---------------------------------------------------------------------------
__device__ __forceinline__ unsigned long long pack2(unsigned lo, unsigned hi) {
    unsigned long long d;
    asm("mov.b64 %0, {%1, %2};" : "=l"(d) : "r"(lo), "r"(hi));
    return d;
}
__device__ __forceinline__ unsigned long long ffma2(unsigned long long a,
                                                    unsigned long long b,
                                                    unsigned long long c) {
    unsigned long long d;
    asm("fma.rn.f32x2 %0, %1, %2, %3;" : "=l"(d) : "l"(a), "l"(b), "l"(c));
    return d;
}
__device__ __forceinline__ unsigned long long fadd2(unsigned long long a,
                                                    unsigned long long b) {
    unsigned long long d;
    asm("add.rn.f32x2 %0, %1, %2;" : "=l"(d) : "l"(a), "l"(b));
    return d;
}
__device__ __forceinline__ float lo32(unsigned long long v) {
    return __uint_as_float((unsigned)v);
}
__device__ __forceinline__ float hi32(unsigned long long v) {
    return __uint_as_float((unsigned)(v >> 32));
}

// ---------------------------------------------------------------------------
// Kernel 1: Poisson input spikes for all T -> Xis output region [t][b][i].
// ---------------------------------------------------------------------------
__global__ void __launch_bounds__(256) prep_spikes(const float* __restrict__ rates,
                                                   const float* __restrict__ noise,
                                                   float* __restrict__ out) {
    int idx = blockIdx.x * blockDim.x + threadIdx.x;
    if (idx >= XIS_SZ) return;
    float rt = rates[idx];
    float nz = noise[idx];
    out[idx] = (nz < __fmul_rn(rt, 1e-3f)) ? 1.0f : 0.0f;
}

// ---------------------------------------------------------------------------
// Kernel 1b: pack ff spike masks: g_mff[t][bg][i] bit b = spike(batch bg*8+b).
// ---------------------------------------------------------------------------
__global__ void __launch_bounds__(256) prep_masks(const float* __restrict__ out) {
    int idx = blockIdx.x * blockDim.x + threadIdx.x;    // t*NBG*NIN
    if (idx >= T_STEPS * NBG * NIN) return;
    int t  = idx / (NBG * NIN);
    int r  = idx - t * (NBG * NIN);
    int bg = r >> 9;
    int i  = r & (NIN - 1);
    unsigned m = 0;
#pragma unroll
    for (int b = 0; b < 8; b++) {
        float f = out[t * (B_SZ * NIN) + (bg * 8 + b) * NIN + i];
        m |= (f != 0.0f ? 1u : 0u) << b;
    }
    g_mff[idx] = (unsigned char)m;
}

// ---------------------------------------------------------------------------
// Kernel 2: fuse Win [A,NIN,N] and Wrec [S,A,N,N] into g_W[k][c].
// ---------------------------------------------------------------------------
__global__ void pack_w(const float* __restrict__ Win,
                       const float* __restrict__ Wrec) {
    const int total4 = KROWS * NC / 4;
    for (int idx = blockIdx.x * blockDim.x + threadIdx.x; idx < total4;
         idx += gridDim.x * blockDim.x) {
        int e = idx << 2;
        int k = e >> 12;              // / 4096
        int c = e & (NC - 1);
        int a = c >> 11;
        int n = c & (N_NEU - 1);
        float4 v;
        if (k < NIN) {
            v = *(const float4*)&Win[(a * NIN + k) * N_NEU + n];
        } else {
            int kr = k - NIN;
            int s  = kr >> 11;
            int m  = kr & (N_NEU - 1);
            v = *(const float4*)&Wrec[(((s * A_AR + a) * N_NEU) + m) * (size_t)N_NEU + n];
        }
        *(float4*)&g_W[e] = v;
    }
}

// ---------------------------------------------------------------------------
// Kernel 3: init: V = 0; g_m8 = [mff(t=0) | zero rec masks].
// ---------------------------------------------------------------------------
__global__ void __launch_bounds__(256) init_state() {
    int idx = blockIdx.x * blockDim.x + threadIdx.x;
    if (idx < NBG * KROWS) {
        int bg = idx / KROWS;
        int k  = idx - bg * KROWS;
        g_m8[idx] = (k < NIN) ? g_mff[bg * NIN + k] : (unsigned char)0;
    }
    if (idx < B_SZ * NC) g_V[idx] = 0.0f;
}

// ---------------------------------------------------------------------------
// Kernel B (per step): mask-driven compact + sparse binary-spike GEMM (R8),
// tuned for SINGLE-WAVE execution: 4 blocks/SM (512 blocks <= 592 slots).
// Grid: (16 col-tiles, 4 bg, 8 by). Block: 8 warps = 4 ksub x 2 cw.
// Phase 1: warps 0..3 read 144 mask bytes for chunk by*4+w, ballot-compact
//   ascending-k active rows + expand exact {0,1} floats into shared.
// Phase 2: 2-row batched register prefetch (depth reduced from 4 to fit the
//   64-reg budget of 4 blocks/SM), ascending-i consume — values and order
//   identical to R8 -> bit-exact.
// Reduce: ksub ascending in-block fold, by ascending fold in step_update.
// ---------------------------------------------------------------------------
struct SmemP1 {
    unsigned list[4][KCHUNK];       // W byte offsets (k * NC * 4), ascending
    float    spk[4][KCHUNK][8];     // expanded spike floats
    int      cnt[4];
};
union SmemU {
    SmemP1 p1;
    unsigned long long sbuf[8][32][17];   // reduce buffer (16 u64 + pad)
};

__device__ __forceinline__ void fma_row(unsigned long long acc[4][4],
                                        float4 wv, const float* __restrict__ sp) {
    float4 sA = *(const float4*)sp;
    float4 sB = *(const float4*)(sp + 4);
    unsigned long long s2[4];
    s2[0] = pack2(__float_as_uint(sA.x), __float_as_uint(sA.y));
    s2[1] = pack2(__float_as_uint(sA.z), __float_as_uint(sA.w));
    s2[2] = pack2(__float_as_uint(sB.x), __float_as_uint(sB.y));
    s2[3] = pack2(__float_as_uint(sB.z), __float_as_uint(sB.w));
    unsigned wb[4] = {__float_as_uint(wv.x), __float_as_uint(wv.y),
                      __float_as_uint(wv.z), __float_as_uint(wv.w)};
#pragma unroll
    for (int c = 0; c < 4; c++) {
        unsigned long long w2 = pack2(wb[c], wb[c]);
#pragma unroll
        for (int j = 0; j < 4; j++)
            acc[c][j] = ffma2(w2, s2[j], acc[c][j]);
    }
}

__global__ void __launch_bounds__(256, 4) step_gemm() {
    __shared__ SmemU sm;

    const int tid  = threadIdx.x;
    const int w    = tid >> 5;
    const int lane = tid & 31;
    const int cw   = w & 1;          // column half within block
    const int ksub = w >> 1;         // 0..3
    const int bg   = blockIdx.y;     // batch group (8 batches)
    const int by   = blockIdx.z;     // partial index
    const int c0   = blockIdx.x * 256 + cw * 128 + lane * 4;

    // ---- Phase 1: warps 0..3 compact chunk (by*4 + w) for this bg ----
    if (w < 4) {
        const int kc = by * 4 + w;
        const int k0 = kc * KCHUNK;
        const unsigned char* __restrict__ mb = &g_m8[bg * KROWS + k0];
        int total = 0;
#pragma unroll
        for (int it = 0; it < 5; it++) {
            int r = it * 32 + lane;
            unsigned msk = (r < KCHUNK) ? (unsigned)mb[r] : 0u;
            bool act = msk != 0u;
            unsigned bal = __ballot_sync(0xFFFFFFFFu, act);
            if (act) {
                int pos = total + __popc(bal & ((1u << lane) - 1u));
                sm.p1.list[w][pos] = (unsigned)(k0 + r) * (NC * 4);
#pragma unroll
                for (int b = 0; b < 8; b++)
                    sm.p1.spk[w][pos][b] = (msk >> b) & 1u ? 1.0f : 0.0f;
            }
            total += __popc(bal);
        }
        if (lane == 0) sm.p1.cnt[w] = total;
    }
    __syncthreads();

    // ---- Phase 2: sparse FMA loop, 2-row batched W prefetch ----
    const int n = sm.p1.cnt[ksub];
    const unsigned* __restrict__ lst = sm.p1.list[ksub];
    const float*    __restrict__ spk = &sm.p1.spk[ksub][0][0];
    const char* __restrict__ wbase = (const char*)g_W + (unsigned)c0 * 4u;

    unsigned long long acc[4][4];
#pragma unroll
    for (int c = 0; c < 4; c++)
#pragma unroll
        for (int j = 0; j < 4; j++) acc[c][j] = 0ull;

    int i = 0;
    for (; i + 2 <= n; i += 2) {
        uint2 off = *(const uint2*)&lst[i];           // one LDS.64: 2 offsets
        float4 wv0 = *(const float4*)(wbase + off.x); // 2 independent LDG.128
        float4 wv1 = *(const float4*)(wbase + off.y);
        fma_row(acc, wv0, &spk[(i + 0) * 8]);
        fma_row(acc, wv1, &spk[(i + 1) * 8]);
    }
    for (; i < n; i++) {
        unsigned off = lst[i];
        float4 wv = *(const float4*)(wbase + off);
        fma_row(acc, wv, &spk[i * 8]);
    }

    __syncthreads();   // phase-1 data consumed; safe to reuse shared

#pragma unroll
    for (int c = 0; c < 4; c++)
#pragma unroll
        for (int j = 0; j < 4; j++) sm.sbuf[w][lane][c * 4 + j] = acc[c][j];
    __syncthreads();

    if (ksub == 0) {
#pragma unroll
        for (int ks = 1; ks < 4; ks++) {
#pragma unroll
            for (int c = 0; c < 4; c++)
#pragma unroll
                for (int j = 0; j < 4; j++)
                    acc[c][j] = fadd2(acc[c][j], sm.sbuf[ks * 2 + cw][lane][c * 4 + j]);
        }
        // transposed, coalesced stores: g_P[by][b][c0..c0+3]
#pragma unroll
        for (int j = 0; j < 4; j++) {
            int b = bg * 8 + 2 * j;
            float4 lo4 = make_float4(lo32(acc[0][j]), lo32(acc[1][j]),
                                     lo32(acc[2][j]), lo32(acc[3][j]));
            float4 hi4 = make_float4(hi32(acc[0][j]), hi32(acc[1][j]),
                                     hi32(acc[2][j]), hi32(acc[3][j]));
            *(float4*)&g_P[(unsigned)((by * B_SZ + b)     * NC) + c0] = lo4;
            *(float4*)&g_P[(unsigned)((by * B_SZ + b + 1) * NC) + c0] = hi4;
        }
    }
}

// ---------------------------------------------------------------------------
// Kernel C (per step): thread = (bg, c) owns all 8 batches of its group.
// Ordered by-ascending reduce of 8 partials, LIF update, threshold, output
// writes, new recurrent mask byte, ff mask copy for t+1. All coalesced.
// ---------------------------------------------------------------------------
__global__ void __launch_bounds__(256) step_update(float* __restrict__ out, int t) {
    int idx = blockIdx.x * blockDim.x + threadIdx.x;   // 0 .. 16383
    if (idx >= NBG * NC) return;
    int bg = idx >> 12;
    int c  = idx & (NC - 1);
    int a  = c >> 11;
    int n  = c & (N_NEU - 1);

    unsigned oldm = g_m8[bg * KROWS + NIN + c];   // previous spikes (8 batches)
    unsigned newm = 0;

#pragma unroll
    for (int b8 = 0; b8 < 8; b8++) {
        int b = bg * 8 + b8;
        float I = g_P[(0 * B_SZ + b) * NC + c];
#pragma unroll
        for (int by = 1; by < NBY; by++)
            I = __fadd_rn(I, g_P[(by * B_SZ + b) * NC + c]);

        float xd   = (oldm >> b8) & 1u ? 1.0f : 0.0f;
        float Vold = g_V[b * NC + c];
        float Vnew = __fadd_rn(__fmul_rn(__fmul_rn(ALPHA_F, Vold),
                                         __fsub_rn(1.0f, xd)), I);
        unsigned s = Vnew >= 1.0f ? 1u : 0u;
        g_V[b * NC + c] = Vnew;
        newm |= s << b8;
        out[XIS_SZ + a * SS_SZ + t * (B_SZ * N_NEU) + b * N_NEU + n] =
            s ? 1.0f : 0.0f;
    }

    g_m8[bg * KROWS + NIN + c] = (unsigned char)newm;
    if (c < NIN && t + 1 < T_STEPS)
        g_m8[bg * KROWS + c] = g_mff[((t + 1) * NBG + bg) * NIN + c];
}

// ---------------------------------------------------------------------------
// Launch: prep (4 kernels) + 100 x (gemm, update). Graph-capturable.
// ---------------------------------------------------------------------------
extern "C" void kernel_launch(void* const* d_in, const int* in_sizes, int n_in,
                              void* d_out, int out_size) {
    const float* rates = (const float*)d_in[0];
    const float* noise = (const float*)d_in[1];
    const float* Win   = (const float*)d_in[2];
    const float* Wrec  = (const float*)d_in[3];
    float* out = (float*)d_out;

    prep_spikes<<<(XIS_SZ + 255) / 256, 256>>>(rates, noise, out);
    prep_masks<<<(T_STEPS * NBG * NIN + 255) / 256, 256>>>(out);
    pack_w<<<1024, 256>>>(Win, Wrec);
    init_state<<<(B_SZ * NC + 255) / 256, 256>>>();

    for (int t = 0; t < T_STEPS; t++) {
        step_gemm<<<dim3(16, NBG, NBY), 256>>>();
        step_update<<<(NBG * NC + 255) / 256, 256>>>(out, t);
    }
}

// round 14
// speedup vs baseline: 2.0604x; 1.0341x over previous
#include <cuda_runtime.h>
#include <cstdint>

// ---------------------------------------------------------------------------
// Problem constants
// ---------------------------------------------------------------------------
#define T_STEPS 100
#define B_SZ    32
#define NIN     512
#define N_NEU   2048
#define A_AR    2
#define NC      4096                    // A*N output columns, c = a*2048+n
#define KROWS   4608                    // NIN + NC input rows
#define KCHUNK  144                     // 4608 / 32 k-chunks
#define NKC     32                      // number of k-chunks
#define NBY     8                       // k-splits (4 chunks each)
#define NBG     4                       // batch groups of 8
#define XIS_SZ  (T_STEPS * B_SZ * NIN)  // 1,638,400
#define SS_SZ   (T_STEPS * B_SZ * N_NEU)// 6,553,600 per area
// alpha = float32(exp(-0.1))
#define ALPHA_F 0.9048374180359595731642491f

// ---------------------------------------------------------------------------
// Device-global scratch (static — no allocation anywhere).
//   g_mff[t][bg][i] : ff spike mask bytes, rewritten fully every launch.
//   g_rec[bg][c]    : recurrent spike mask bytes for the CURRENT step;
//                     zeroed by mega_prep每 launch, rewritten by step_update.
// No state survives a replay incorrectly: every byte either is rewritten
// deterministically each launch or zeroed in mega_prep.
// ---------------------------------------------------------------------------
__device__ float         g_W[KROWS * NC];              // fused weights [k][c]
__device__ float         g_V[B_SZ * NC];               // membrane V [b][c]
__device__ float         g_P[NBY * B_SZ * NC];         // partials [by][b][c]
__device__ unsigned char g_mff[T_STEPS * NBG * NIN];   // ff masks per t
__device__ unsigned char g_rec[NBG * NC];              // recurrent masks

// ---------------------------------------------------------------------------
// Packed f32x2 helpers (sm_103a) — immune to fast-math contraction
// ---------------------------------------------------------------------------
__device__ __forceinline__ unsigned long long pack2(unsigned lo, unsigned hi) {
    unsigned long long d;
    asm("mov.b64 %0, {%1, %2};" : "=l"(d) : "r"(lo), "r"(hi));
    return d;
}
__device__ __forceinline__ unsigned long long ffma2(unsigned long long a,
                                                    unsigned long long b,
                                                    unsigned long long c) {
    unsigned long long d;
    asm("fma.rn.f32x2 %0, %1, %2, %3;" : "=l"(d) : "l"(a), "l"(b), "l"(c));
    return d;
}
__device__ __forceinline__ unsigned long long fadd2(unsigned long long a,
                                                    unsigned long long b) {
    unsigned long long d;
    asm("add.rn.f32x2 %0, %1, %2;" : "=l"(d) : "l"(a), "l"(b));
    return d;
}
__device__ __forceinline__ float lo32(unsigned long long v) {
    return __uint_as_float((unsigned)v);
}
__device__ __forceinline__ float hi32(unsigned long long v) {
    return __uint_as_float((unsigned)(v >> 32));
}

// ---------------------------------------------------------------------------
// Kernel 1 (the ONLY prep launch): three independent grid-stride jobs,
// all deterministic and atomic-free.
//  A) One thread per (t, bg, i): computes the 8 batch spikes, writes the 8
//     output floats (Xis region, [t][b][i]) and the g_mff byte.
//  B) Fuse Win [A,NIN,N] + Wrec [S,A,N,N] into g_W[k][c].
//  C) Zero V and g_rec (fresh state every launch/replay).
// ---------------------------------------------------------------------------
__global__ void __launch_bounds__(256) mega_prep(const float* __restrict__ rates,
                                                 const float* __restrict__ noise,
                                                 const float* __restrict__ Win,
                                                 const float* __restrict__ Wrec,
                                                 float* __restrict__ out) {
    const int gsz  = gridDim.x * blockDim.x;
    const int tid0 = blockIdx.x * blockDim.x + threadIdx.x;

    // ---- Job A: spikes + ff mask bytes ----
    const int na = T_STEPS * NBG * NIN;
    for (int idx = tid0; idx < na; idx += gsz) {
        int t  = idx / (NBG * NIN);
        int r  = idx - t * (NBG * NIN);
        int bg = r >> 9;               // / NIN
        int i  = r & (NIN - 1);
        unsigned m = 0;
#pragma unroll
        for (int b8 = 0; b8 < 8; b8++) {
            int e = (t * B_SZ + bg * 8 + b8) * NIN + i;
            float rt = rates[e];
            float nz = noise[e];
            bool sp = nz < __fmul_rn(rt, 1e-3f);
            out[e] = sp ? 1.0f : 0.0f;
            m |= (sp ? 1u : 0u) << b8;
        }
        g_mff[idx] = (unsigned char)m;
    }

    // ---- Job B: pack W ----
    const int total4 = KROWS * NC / 4;
    for (int idx = tid0; idx < total4; idx += gsz) {
        int e = idx << 2;
        int k = e >> 12;              // / 4096
        int c = e & (NC - 1);
        int a = c >> 11;
        int n = c & (N_NEU - 1);
        float4 v;
        if (k < NIN) {
            v = *(const float4*)&Win[(a * NIN + k) * N_NEU + n];
        } else {
            int kr = k - NIN;
            int s  = kr >> 11;
            int m  = kr & (N_NEU - 1);
            v = *(const float4*)&Wrec[(((s * A_AR + a) * N_NEU) + m) * (size_t)N_NEU + n];
        }
        *(float4*)&g_W[e] = v;
    }

    // ---- Job C: zero V + recurrent masks ----
    for (int idx = tid0; idx < B_SZ * NC; idx += gsz) g_V[idx] = 0.0f;
    for (int idx = tid0; idx < NBG * NC / 4; idx += gsz)
        ((unsigned*)g_rec)[idx] = 0u;
}

// ---------------------------------------------------------------------------
// Kernel B (per step): mask-driven compact + sparse binary-spike GEMM.
// BYTE-IDENTICAL arithmetic to the R12 passing kernel (4 blocks/SM, single
// wave). Grid: (16 col-tiles, 4 bg, 8 by). Block: 8 warps = 4 ksub x 2 cw.
// Phase 1 now sources mask bytes directly: ff rows (k < 512) from g_mff[t],
// recurrent rows from g_rec — same values as the old g_m8 copy, so lists and
// all downstream arithmetic are unchanged.
// ---------------------------------------------------------------------------
struct SmemP1 {
    unsigned list[4][KCHUNK];       // W byte offsets (k * NC * 4), ascending
    float    spk[4][KCHUNK][8];     // expanded spike floats
    int      cnt[4];
};
union SmemU {
    SmemP1 p1;
    unsigned long long sbuf[8][32][17];   // reduce buffer (16 u64 + pad)
};

__device__ __forceinline__ void fma_row(unsigned long long acc[4][4],
                                        float4 wv, const float* __restrict__ sp) {
    float4 sA = *(const float4*)sp;
    float4 sB = *(const float4*)(sp + 4);
    unsigned long long s2[4];
    s2[0] = pack2(__float_as_uint(sA.x), __float_as_uint(sA.y));
    s2[1] = pack2(__float_as_uint(sA.z), __float_as_uint(sA.w));
    s2[2] = pack2(__float_as_uint(sB.x), __float_as_uint(sB.y));
    s2[3] = pack2(__float_as_uint(sB.z), __float_as_uint(sB.w));
    unsigned wb[4] = {__float_as_uint(wv.x), __float_as_uint(wv.y),
                      __float_as_uint(wv.z), __float_as_uint(wv.w)};
#pragma unroll
    for (int c = 0; c < 4; c++) {
        unsigned long long w2 = pack2(wb[c], wb[c]);
#pragma unroll
        for (int j = 0; j < 4; j++)
            acc[c][j] = ffma2(w2, s2[j], acc[c][j]);
    }
}

__global__ void __launch_bounds__(256, 4) step_gemm(int t) {
    __shared__ SmemU sm;

    const int tid  = threadIdx.x;
    const int w    = tid >> 5;
    const int lane = tid & 31;
    const int cw   = w & 1;          // column half within block
    const int ksub = w >> 1;         // 0..3
    const int bg   = blockIdx.y;     // batch group (8 batches)
    const int by   = blockIdx.z;     // partial index
    const int c0   = blockIdx.x * 256 + cw * 128 + lane * 4;

    // ---- Phase 1: warps 0..3 compact chunk (by*4 + w) for this bg ----
    if (w < 4) {
        const int kc = by * 4 + w;
        const int k0 = kc * KCHUNK;
        const unsigned char* __restrict__ mff_t = &g_mff[(t * NBG + bg) * NIN];
        const unsigned char* __restrict__ recb  = &g_rec[bg * NC];
        int total = 0;
#pragma unroll
        for (int it = 0; it < 5; it++) {
            int r = it * 32 + lane;
            int k = k0 + r;
            unsigned msk = 0u;
            if (r < KCHUNK)
                msk = (k < NIN) ? (unsigned)mff_t[k] : (unsigned)recb[k - NIN];
            bool act = msk != 0u;
            unsigned bal = __ballot_sync(0xFFFFFFFFu, act);
            if (act) {
                int pos = total + __popc(bal & ((1u << lane) - 1u));
                sm.p1.list[w][pos] = (unsigned)k * (NC * 4);
#pragma unroll
                for (int b = 0; b < 8; b++)
                    sm.p1.spk[w][pos][b] = (msk >> b) & 1u ? 1.0f : 0.0f;
            }
            total += __popc(bal);
        }
        if (lane == 0) sm.p1.cnt[w] = total;
    }
    __syncthreads();

    // ---- Phase 2: sparse FMA loop, 2-row batched W prefetch ----
    const int n = sm.p1.cnt[ksub];
    const unsigned* __restrict__ lst = sm.p1.list[ksub];
    const float*    __restrict__ spk = &sm.p1.spk[ksub][0][0];
    const char* __restrict__ wbase = (const char*)g_W + (unsigned)c0 * 4u;

    unsigned long long acc[4][4];
#pragma unroll
    for (int c = 0; c < 4; c++)
#pragma unroll
        for (int j = 0; j < 4; j++) acc[c][j] = 0ull;

    int i = 0;
    for (; i + 2 <= n; i += 2) {
        uint2 off = *(const uint2*)&lst[i];           // one LDS.64: 2 offsets
        float4 wv0 = *(const float4*)(wbase + off.x); // 2 independent LDG.128
        float4 wv1 = *(const float4*)(wbase + off.y);
        fma_row(acc, wv0, &spk[(i + 0) * 8]);
        fma_row(acc, wv1, &spk[(i + 1) * 8]);
    }
    for (; i < n; i++) {
        unsigned off = lst[i];
        float4 wv = *(const float4*)(wbase + off);
        fma_row(acc, wv, &spk[i * 8]);
    }

    __syncthreads();   // phase-1 data consumed; safe to reuse shared

#pragma unroll
    for (int c = 0; c < 4; c++)
#pragma unroll
        for (int j = 0; j < 4; j++) sm.sbuf[w][lane][c * 4 + j] = acc[c][j];
    __syncthreads();

    if (ksub == 0) {
#pragma unroll
        for (int ks = 1; ks < 4; ks++) {
#pragma unroll
            for (int c = 0; c < 4; c++)
#pragma unroll
                for (int j = 0; j < 4; j++)
                    acc[c][j] = fadd2(acc[c][j], sm.sbuf[ks * 2 + cw][lane][c * 4 + j]);
        }
        // transposed, coalesced stores: g_P[by][b][c0..c0+3]
#pragma unroll
        for (int j = 0; j < 4; j++) {
            int b = bg * 8 + 2 * j;
            float4 lo4 = make_float4(lo32(acc[0][j]), lo32(acc[1][j]),
                                     lo32(acc[2][j]), lo32(acc[3][j]));
            float4 hi4 = make_float4(hi32(acc[0][j]), hi32(acc[1][j]),
                                     hi32(acc[2][j]), hi32(acc[3][j]));
            *(float4*)&g_P[(unsigned)((by * B_SZ + b)     * NC) + c0] = lo4;
            *(float4*)&g_P[(unsigned)((by * B_SZ + b + 1) * NC) + c0] = hi4;
        }
    }
}

// ---------------------------------------------------------------------------
// Kernel C (per step): thread = (bg, c) owns all 8 batches of its group.
// BYTE-IDENTICAL arithmetic to R12: by-ascending reduce of 8 partials, LIF
// update, threshold, output writes, new recurrent mask byte. (No ff copy —
// gemm reads g_mff[t] directly.)
// ---------------------------------------------------------------------------
__global__ void __launch_bounds__(256) step_update(float* __restrict__ out, int t) {
    int idx = blockIdx.x * blockDim.x + threadIdx.x;   // 0 .. 16383
    if (idx >= NBG * NC) return;
    int bg = idx >> 12;
    int c  = idx & (NC - 1);
    int a  = c >> 11;
    int n  = c & (N_NEU - 1);

    unsigned oldm = g_rec[bg * NC + c];   // previous spikes (8 batches)
    unsigned newm = 0;

#pragma unroll
    for (int b8 = 0; b8 < 8; b8++) {
        int b = bg * 8 + b8;
        float I = g_P[(0 * B_SZ + b) * NC + c];
#pragma unroll
        for (int by = 1; by < NBY; by++)
            I = __fadd_rn(I, g_P[(by * B_SZ + b) * NC + c]);

        float xd   = (oldm >> b8) & 1u ? 1.0f : 0.0f;
        float Vold = g_V[b * NC + c];
        float Vnew = __fadd_rn(__fmul_rn(__fmul_rn(ALPHA_F, Vold),
                                         __fsub_rn(1.0f, xd)), I);
        unsigned s = Vnew >= 1.0f ? 1u : 0u;
        g_V[b * NC + c] = Vnew;
        newm |= s << b8;
        out[XIS_SZ + a * SS_SZ + t * (B_SZ * N_NEU) + b * N_NEU + n] =
            s ? 1.0f : 0.0f;
    }

    g_rec[bg * NC + c] = (unsigned char)newm;
}

// ---------------------------------------------------------------------------
// Launch: 1 prep kernel + 100 x (gemm, update). Graph-capturable, replay-
// deterministic (all persistent state rewritten or zeroed each call).
// Launch #4 (ncu capture slot) = step_gemm at t=1.
// ---------------------------------------------------------------------------
extern "C" void kernel_launch(void* const* d_in, const int* in_sizes, int n_in,
                              void* d_out, int out_size) {
    const float* rates = (const float*)d_in[0];
    const float* noise = (const float*)d_in[1];
    const float* Win   = (const float*)d_in[2];
    const float* Wrec  = (const float*)d_in[3];
    float* out = (float*)d_out;

    mega_prep<<<2048, 256>>>(rates, noise, Win, Wrec, out);

    for (int t = 0; t < T_STEPS; t++) {
        step_gemm<<<dim3(16, NBG, NBY), 256>>>(t);
        step_update<<<(NBG * NC + 255) / 256, 256>>>(out, t);
    }
}